// round 5
// baseline (speedup 1.0000x reference)
#include <cuda_runtime.h>
#include <cuda_bf16.h>
#include <cstdint>

// ---------------------------------------------------------------------------
// MAB: q=Q@Wq+bq; k=K@Wk+bk; v=K@Wv+bv  (heads interleaved: d = h*64+dh)
//      S = (q.k^T)/8 per head, mask==0 -> -1e9, softmax (flash/online)
//      o = q + S@v ; O=LN0(o) ; O = LN1(O + relu(O@Wo + bo))
// B=8, N=1024, D=512, H=8, DH=64
// GEMMs: warp-level mma.sync bf16 with 3-way fp32 split (no tcgen05 — the
//        harness targets plain sm_103, which rejects tcgen05 PTX).
// Attention: fp32 SIMT flash with packed f32x2 FFMA.
// ---------------------------------------------------------------------------

#define BATCH 8
#define NTOK  1024
#define DMODEL 512
#define NHEAD 8
#define DHEAD 64
#define NROWS (BATCH * NTOK)   // 8192

typedef unsigned long long u64;

__device__ __forceinline__ void ffma2(u64& d, u64 a, u64 b) {
    asm("fma.rn.f32x2 %0, %1, %2, %0;" : "+l"(d) : "l"(a), "l"(b));
}
__device__ __forceinline__ u64 pk2(float x, float y) {
    u64 r; asm("mov.b64 %0, {%1, %2};" : "=l"(r) : "f"(x), "f"(y)); return r;
}
__device__ __forceinline__ float2 up2(u64 v) {
    float2 r; asm("mov.b64 {%0, %1}, %2;" : "=f"(r.x), "=f"(r.y) : "l"(v)); return r;
}
__device__ __forceinline__ void fmul2_(u64& d, u64 a) {
    asm("mul.rn.f32x2 %0, %0, %1;" : "+l"(d) : "l"(a));
}

__device__ __forceinline__ uint32_t smem_u32(const void* p) {
    uint32_t a;
    asm("{ .reg .u64 t; cvta.to.shared.u64 t, %1; cvt.u32.u64 %0, t; }"
        : "=r"(a) : "l"(p));
    return a;
}
// pack two fp32 into bf16x2 (lo -> low half, hi -> high half)
__device__ __forceinline__ unsigned pkbf(float lo, float hi) {
    unsigned r; asm("cvt.rn.bf16x2.f32 %0, %1, %2;" : "=r"(r) : "f"(hi), "f"(lo));
    return r;
}
__device__ __forceinline__ float bfr(float x) {
    return __bfloat162float(__float2bfloat16_rn(x));
}

__device__ __forceinline__ void ldsm_x4(uint32_t (&r)[4], uint32_t addr) {
    asm volatile("ldmatrix.sync.aligned.m8n8.x4.shared.b16 {%0,%1,%2,%3}, [%4];"
                 : "=r"(r[0]), "=r"(r[1]), "=r"(r[2]), "=r"(r[3]) : "r"(addr));
}
__device__ __forceinline__ void ldsm_x2t(uint32_t (&r)[2], uint32_t addr) {
    asm volatile("ldmatrix.sync.aligned.m8n8.x2.trans.shared.b16 {%0,%1}, [%2];"
                 : "=r"(r[0]), "=r"(r[1]) : "r"(addr));
}
__device__ __forceinline__ void mma_bf16(float (&c)[4], const uint32_t (&a)[4],
                                         const uint32_t (&b)[2]) {
    asm volatile("mma.sync.aligned.m16n8k16.row.col.f32.bf16.bf16.f32 "
                 "{%0,%1,%2,%3}, {%4,%5,%6,%7}, {%8,%9}, {%0,%1,%2,%3};"
                 : "+f"(c[0]), "+f"(c[1]), "+f"(c[2]), "+f"(c[3])
                 : "r"(a[0]), "r"(a[1]), "r"(a[2]), "r"(a[3]),
                   "r"(b[0]), "r"(b[1]));
}

// scratch (no allocations allowed)
__device__ float g_q[BATCH * NTOK * DMODEL];
__device__ float g_k[BATCH * NTOK * DMODEL];
__device__ float g_v[BATCH * NTOK * DMODEL];
__device__ float g_o[BATCH * NTOK * DMODEL];
__device__ float g_ln0[BATCH * NTOK * DMODEL];
__device__ float g_tmp[BATCH * NTOK * DMODEL];

// ---------------------------------------------------------------------------
// HMMA GEMM: C[8192,512] = A[8192,512] @ W[512,512] + bias (opt relu)
// CTA tile 128x64, BK=32, 256 threads = 8 warps (4m x 2n), warp tile 32x32.
// bf16 3-split: C += Ahi*Bhi + Ahi*Blo + Alo*Bhi  (fp32 accum).
// ---------------------------------------------------------------------------
#define TCM 128
#define TCN 64
#define TBK 32
#define NCHUNK (DMODEL / TBK)       // 16
#define ASTR 40                      // bf16 elems per A row (32 + 8 pad)
#define BSTR 72                      // bf16 elems per B row (64 + 8 pad)
#define AHI_E 0
#define ALO_E (TCM * ASTR)           // 5120
#define BHI_E (2 * TCM * ASTR)       // 10240
#define BLO_E (2 * TCM * ASTR + TBK * BSTR)   // 12544
#define BUF_E (2 * TCM * ASTR + 2 * TBK * BSTR)  // 14848 bf16 elems
#define GEMM_DSMEM (2 * BUF_E * 2)   // 59392 bytes

__global__ __launch_bounds__(256)
void gemm_mma_kernel(const float* __restrict__ A, const float* __restrict__ W,
                     const float* __restrict__ bias, float* __restrict__ C,
                     int relu)
{
    extern __shared__ __align__(16) __nv_bfloat16 dsm[];

    const int t    = threadIdx.x;
    const int lane = t & 31;
    const int wid  = t >> 5;
    const int bm   = blockIdx.y * TCM;
    const int bn   = blockIdx.x * TCN;
    const int m0   = (wid >> 1) << 5;    // warp m offset 0..96
    const int n0   = (wid & 1) << 5;     // warp n offset 0/32
    const int lr   = lane & 15;
    const int lc   = lane >> 4;

    // global staging addresses (A: row t>>1, cols (t&1)*16+4l; W: k t>>3, n (t&7)*8)
    const int arow = t >> 1;
    const int acol = (t & 1) << 4;
    const int brow = t >> 3;
    const int bcol = (t & 7) << 3;

    float4 ra[4];
    float4 rw[2];

    // ---- load + convert + store one chunk ----
    auto load_regs = [&](int kc) {
        const float* Ab = A + (size_t)(bm + arow) * DMODEL + kc + acol;
#pragma unroll
        for (int l = 0; l < 4; l++) ra[l] = *(const float4*)&Ab[l << 2];
        const float* Wb = W + (size_t)(kc + brow) * DMODEL + bn + bcol;
        rw[0] = *(const float4*)&Wb[0];
        rw[1] = *(const float4*)&Wb[4];
    };
    auto store_buf = [&](__nv_bfloat16* buf) {
        // A
#pragma unroll
        for (int l = 0; l < 4; l++) {
            float4 a = ra[l];
            float hx = bfr(a.x), hy = bfr(a.y), hz = bfr(a.z), hw = bfr(a.w);
            uint2 hv, lv;
            hv.x = pkbf(a.x, a.y);           hv.y = pkbf(a.z, a.w);
            lv.x = pkbf(a.x - hx, a.y - hy); lv.y = pkbf(a.z - hz, a.w - hw);
            int e = arow * ASTR + acol + (l << 2);
            *(uint2*)&buf[AHI_E + e] = hv;
            *(uint2*)&buf[ALO_E + e] = lv;
        }
        // B
        {
            float h0 = bfr(rw[0].x), h1 = bfr(rw[0].y), h2 = bfr(rw[0].z), h3 = bfr(rw[0].w);
            float h4 = bfr(rw[1].x), h5 = bfr(rw[1].y), h6 = bfr(rw[1].z), h7 = bfr(rw[1].w);
            uint4 hv, lv;
            hv.x = pkbf(rw[0].x, rw[0].y); hv.y = pkbf(rw[0].z, rw[0].w);
            hv.z = pkbf(rw[1].x, rw[1].y); hv.w = pkbf(rw[1].z, rw[1].w);
            lv.x = pkbf(rw[0].x - h0, rw[0].y - h1);
            lv.y = pkbf(rw[0].z - h2, rw[0].w - h3);
            lv.z = pkbf(rw[1].x - h4, rw[1].y - h5);
            lv.w = pkbf(rw[1].z - h6, rw[1].w - h7);
            int e = brow * BSTR + bcol;
            *(uint4*)&buf[BHI_E + e] = hv;
            *(uint4*)&buf[BLO_E + e] = lv;
        }
    };

    float c[2][4][4];
#pragma unroll
    for (int ma = 0; ma < 2; ma++)
#pragma unroll
        for (int na = 0; na < 4; na++)
#pragma unroll
            for (int r = 0; r < 4; r++) c[ma][na][r] = 0.f;

    // prologue: chunk 0
    load_regs(0);
    store_buf(dsm);
    __syncthreads();

    for (int ck = 0; ck < NCHUNK; ck++) {
        __nv_bfloat16* cur = dsm + (ck & 1) * BUF_E;
        if (ck + 1 < NCHUNK) load_regs((ck + 1) * TBK);

        // ---- fragments from cur ----
        uint32_t ahi[2][2][4], alo[2][2][4];   // [ka][ma]
        uint32_t bhi[2][4][2], blo[2][4][2];   // [ka][na]
#pragma unroll
        for (int ka = 0; ka < 2; ka++) {
#pragma unroll
            for (int ma = 0; ma < 2; ma++) {
                int e = (m0 + (ma << 4) + lr) * ASTR + (ka << 4) + (lc << 3);
                ldsm_x4(ahi[ka][ma], smem_u32(&cur[AHI_E + e]));
                ldsm_x4(alo[ka][ma], smem_u32(&cur[ALO_E + e]));
            }
#pragma unroll
            for (int na = 0; na < 4; na++) {
                int e = ((ka << 4) + lr) * BSTR + n0 + (na << 3);
                ldsm_x2t(bhi[ka][na], smem_u32(&cur[BHI_E + e]));
                ldsm_x2t(blo[ka][na], smem_u32(&cur[BLO_E + e]));
            }
        }
#pragma unroll
        for (int ka = 0; ka < 2; ka++)
#pragma unroll
            for (int ma = 0; ma < 2; ma++)
#pragma unroll
                for (int na = 0; na < 4; na++) {
                    mma_bf16(c[ma][na], ahi[ka][ma], bhi[ka][na]);
                    mma_bf16(c[ma][na], ahi[ka][ma], blo[ka][na]);
                    mma_bf16(c[ma][na], alo[ka][ma], bhi[ka][na]);
                }

        if (ck + 1 < NCHUNK) store_buf(dsm + ((ck + 1) & 1) * BUF_E);
        __syncthreads();
    }

    // ---- epilogue: bias (+relu), write C ----
#pragma unroll
    for (int ma = 0; ma < 2; ma++) {
        int row = bm + m0 + (ma << 4) + (lane >> 2);
#pragma unroll
        for (int na = 0; na < 4; na++) {
            int col = bn + n0 + (na << 3) + ((lane & 3) << 1);
            float b0 = bias[col], b1 = bias[col + 1];
            float v0 = c[ma][na][0] + b0, v1 = c[ma][na][1] + b1;
            float v2 = c[ma][na][2] + b0, v3 = c[ma][na][3] + b1;
            if (relu) {
                v0 = fmaxf(v0, 0.f); v1 = fmaxf(v1, 0.f);
                v2 = fmaxf(v2, 0.f); v3 = fmaxf(v3, 0.f);
            }
            *(float2*)&C[(size_t)row * DMODEL + col]       = make_float2(v0, v1);
            *(float2*)&C[(size_t)(row + 8) * DMODEL + col] = make_float2(v2, v3);
        }
    }
}

// ---------------------------------------------------------------------------
// Flash attention: block = (b, h, 64 query rows). Online softmax, KC=64 chunks.
// Phase 1: 4 rows x 4 cols per thread (16x16 thread grid).
// Phase 2: 2 rows x 8 dims per thread (32x8 thread grid), vectorized sP reads.
// ---------------------------------------------------------------------------
#define TQ 64
#define KC 64
#define STR 68

#define ATTN_SMEM ((4 * 64 * STR + NTOK + 3 * TQ) * 4)

__global__ __launch_bounds__(256) void attn_kernel(
    const float* __restrict__ q, const float* __restrict__ k,
    const float* __restrict__ v, const int* __restrict__ mask,
    float* __restrict__ o)
{
    extern __shared__ __align__(16) float sm[];
    float* sQ   = sm;                 // [DH][STR]  q transposed: sQ[d*STR + i]
    float* sK   = sQ + 64 * STR;      // [DH][STR]  k transposed: sK[d*STR + j]
    float* sV   = sK + 64 * STR;      // [KC][STR]  v natural:    sV[j*STR + d]
    float* sP   = sV + 64 * STR;      // [TQ][STR]  probs:        sP[i*STR + j]
    float* mk   = sP + 64 * STR;      // [NTOK]
    float* mrun = mk + NTOK;          // [TQ]
    float* lrun = mrun + TQ;          // [TQ]
    float* salp = lrun + TQ;          // [TQ] per-chunk alpha

    const int t  = threadIdx.x;       // 256
    const int b  = blockIdx.z;
    const int h  = blockIdx.y;
    const int q0 = blockIdx.x * TQ;
    const int tx = t & 15;
    const int ty = t >> 4;
    const int i0 = ty << 2;           // phase-1: 4 rows
    const int j0 = tx << 2;           // phase-1: 4 score cols
    const int ty2 = t >> 3;
    const int tx2 = t & 7;
    const int i2 = ty2 << 1;          // phase-2: 2 rows
    const int d2 = tx2 << 3;          // phase-2: 8 head dims

    // load Q tile transposed + mask + stats init
#pragma unroll
    for (int l = 0; l < 4; l++) {
        int idx = t + (l << 8);
        int i   = idx >> 4;
        int dd  = (idx & 15) << 2;
        float4 qv = *(const float4*)&q[((size_t)(b * NTOK + q0 + i)) * DMODEL + h * DHEAD + dd];
        sQ[(dd + 0) * STR + i] = qv.x; sQ[(dd + 1) * STR + i] = qv.y;
        sQ[(dd + 2) * STR + i] = qv.z; sQ[(dd + 3) * STR + i] = qv.w;
    }
    for (int j = t; j < NTOK; j += 256)
        mk[j] = (mask[b * NTOK + j] == 0) ? 0.f : 1.f;
    if (t < TQ) { mrun[t] = -1e30f; lrun[t] = 0.f; }

    u64 o2[2][4];                     // 2 rows x 4 d-pairs (packed along d)
#pragma unroll
    for (int r = 0; r < 2; r++)
#pragma unroll
        for (int p = 0; p < 4; p++) o2[r][p] = 0ull;

    for (int kc = 0; kc < NTOK; kc += KC) {
        __syncthreads();              // prev phase-2 readers done
        // load K chunk transposed + V chunk natural
#pragma unroll
        for (int l = 0; l < 4; l++) {
            int idx = t + (l << 8);
            int j   = idx >> 4;
            int dd  = (idx & 15) << 2;
            size_t base = ((size_t)(b * NTOK + kc + j)) * DMODEL + h * DHEAD + dd;
            float4 kv4 = *(const float4*)&k[base];
            sK[(dd + 0) * STR + j] = kv4.x; sK[(dd + 1) * STR + j] = kv4.y;
            sK[(dd + 2) * STR + j] = kv4.z; sK[(dd + 3) * STR + j] = kv4.w;
            *(float4*)&sV[j * STR + dd] = *(const float4*)&v[base];
        }
        __syncthreads();

        // ---- phase 1: S = q.k^T (4x4 tile, packed along i) ----
        u64 sp[2][4];
#pragma unroll
        for (int p = 0; p < 2; p++)
#pragma unroll
            for (int j = 0; j < 4; j++) sp[p][j] = 0ull;

#pragma unroll 8
        for (int d = 0; d < DHEAD; d++) {
            ulonglong2 qp = *(const ulonglong2*)&sQ[d * STR + i0];
            float4 kv4 = *(const float4*)&sK[d * STR + j0];
            u64 k0p = pk2(kv4.x, kv4.x), k1p = pk2(kv4.y, kv4.y);
            u64 k2p = pk2(kv4.z, kv4.z), k3p = pk2(kv4.w, kv4.w);
            ffma2(sp[0][0], qp.x, k0p); ffma2(sp[0][1], qp.x, k1p);
            ffma2(sp[0][2], qp.x, k2p); ffma2(sp[0][3], qp.x, k3p);
            ffma2(sp[1][0], qp.y, k0p); ffma2(sp[1][1], qp.y, k1p);
            ffma2(sp[1][2], qp.y, k2p); ffma2(sp[1][3], qp.y, k3p);
        }

        float sv_[4][4];
#pragma unroll
        for (int p = 0; p < 2; p++)
#pragma unroll
            for (int j = 0; j < 4; j++) {
                float2 u = up2(sp[p][j]);
                sv_[2 * p + 0][j] = u.x;
                sv_[2 * p + 1][j] = u.y;
            }
        float fl[4];
#pragma unroll
        for (int jj = 0; jj < 4; jj++) fl[jj] = mk[kc + j0 + jj];

#pragma unroll
        for (int ii = 0; ii < 4; ii++) {
            float s0 = (fl[0] != 0.f) ? sv_[ii][0] * 0.125f : -1e9f;
            float s1 = (fl[1] != 0.f) ? sv_[ii][1] * 0.125f : -1e9f;
            float s2 = (fl[2] != 0.f) ? sv_[ii][2] * 0.125f : -1e9f;
            float s3 = (fl[3] != 0.f) ? sv_[ii][3] * 0.125f : -1e9f;
            float rmx = fmaxf(fmaxf(s0, s1), fmaxf(s2, s3));
#pragma unroll
            for (int off = 8; off; off >>= 1)
                rmx = fmaxf(rmx, __shfl_xor_sync(0xffffffffu, rmx, off));
            int i = i0 + ii;
            float mold = mrun[i];
            float mnew = fmaxf(mold, rmx);
            float a    = __expf(mold - mnew);
            float p0 = __expf(s0 - mnew), p1 = __expf(s1 - mnew);
            float p2 = __expf(s2 - mnew), p3 = __expf(s3 - mnew);
            float rs = (p0 + p1) + (p2 + p3);
#pragma unroll
            for (int off = 8; off; off >>= 1)
                rs += __shfl_xor_sync(0xffffffffu, rs, off);
            if (tx == 0) { mrun[i] = mnew; lrun[i] = lrun[i] * a + rs; salp[i] = a; }
            *(float4*)&sP[i * STR + j0] = make_float4(p0, p1, p2, p3);
        }
        __syncthreads();   // sP + salp visible to phase-2 mapping

        // ---- phase 2: O = O*alpha + P @ V (2 rows x 8 dims, packed along d) ----
        {
            u64 a0 = pk2(salp[i2], salp[i2]);
            u64 a1 = pk2(salp[i2 + 1], salp[i2 + 1]);
#pragma unroll
            for (int p = 0; p < 4; p++) { fmul2_(o2[0][p], a0); fmul2_(o2[1][p], a1); }
        }
#pragma unroll 2
        for (int j = 0; j < KC; j += 4) {
            float4 p0 = *(const float4*)&sP[i2 * STR + j];
            float4 p1 = *(const float4*)&sP[(i2 + 1) * STR + j];
            float pa0[4] = {p0.x, p0.y, p0.z, p0.w};
            float pa1[4] = {p1.x, p1.y, p1.z, p1.w};
#pragma unroll
            for (int jj = 0; jj < 4; jj++) {
                ulonglong2 v0 = *(const ulonglong2*)&sV[(j + jj) * STR + d2];
                ulonglong2 v1 = *(const ulonglong2*)&sV[(j + jj) * STR + d2 + 4];
                u64 pp0 = pk2(pa0[jj], pa0[jj]);
                u64 pp1 = pk2(pa1[jj], pa1[jj]);
                ffma2(o2[0][0], pp0, v0.x); ffma2(o2[0][1], pp0, v0.y);
                ffma2(o2[0][2], pp0, v1.x); ffma2(o2[0][3], pp0, v1.y);
                ffma2(o2[1][0], pp1, v0.x); ffma2(o2[1][1], pp1, v0.y);
                ffma2(o2[1][2], pp1, v1.x); ffma2(o2[1][3], pp1, v1.y);
            }
        }
    }

    // ---- final: normalize, add residual q, store (2 rows x 8 dims) ----
#pragma unroll
    for (int r = 0; r < 2; r++) {
        int i = i2 + r;
        float inv = 1.f / lrun[i];
        float2 u0 = up2(o2[r][0]);
        float2 u1 = up2(o2[r][1]);
        float2 u2 = up2(o2[r][2]);
        float2 u3 = up2(o2[r][3]);
        float4 ra, rb;
        ra.x = u0.x * inv + sQ[(d2 + 0) * STR + i];
        ra.y = u0.y * inv + sQ[(d2 + 1) * STR + i];
        ra.z = u1.x * inv + sQ[(d2 + 2) * STR + i];
        ra.w = u1.y * inv + sQ[(d2 + 3) * STR + i];
        rb.x = u2.x * inv + sQ[(d2 + 4) * STR + i];
        rb.y = u2.y * inv + sQ[(d2 + 5) * STR + i];
        rb.z = u3.x * inv + sQ[(d2 + 6) * STR + i];
        rb.w = u3.y * inv + sQ[(d2 + 7) * STR + i];
        size_t base = ((size_t)(b * NTOK + q0 + i)) * DMODEL + h * DHEAD + d2;
        *(float4*)&o[base]     = ra;
        *(float4*)&o[base + 4] = rb;
    }
}

// ---------------------------------------------------------------------------
// LayerNorm over 512 (optionally x = x1 + x2 first). 128 threads per row.
// ---------------------------------------------------------------------------
__global__ void ln_kernel(const float* __restrict__ x1,
                          const float* __restrict__ x2,
                          const float* __restrict__ g,
                          const float* __restrict__ bb,
                          float* __restrict__ y)
{
    __shared__ float ws[4], ws2[4];
    int row = blockIdx.x;
    int t   = threadIdx.x;          // 128
    int c0  = t * 4;

    float4 xv = *(const float4*)&x1[(size_t)row * DMODEL + c0];
    if (x2) {
        float4 a = *(const float4*)&x2[(size_t)row * DMODEL + c0];
        xv.x += a.x; xv.y += a.y; xv.z += a.z; xv.w += a.w;
    }
    float s = xv.x + xv.y + xv.z + xv.w;
#pragma unroll
    for (int o = 16; o; o >>= 1) s += __shfl_xor_sync(~0u, s, o);
    if ((t & 31) == 0) ws[t >> 5] = s;
    __syncthreads();
    float mean = (ws[0] + ws[1] + ws[2] + ws[3]) * (1.f / DMODEL);

    float dx = xv.x - mean, dy = xv.y - mean, dz = xv.z - mean, dw = xv.w - mean;
    float s2 = dx * dx + dy * dy + dz * dz + dw * dw;
#pragma unroll
    for (int o = 16; o; o >>= 1) s2 += __shfl_xor_sync(~0u, s2, o);
    if ((t & 31) == 0) ws2[t >> 5] = s2;
    __syncthreads();
    float var = (ws2[0] + ws2[1] + ws2[2] + ws2[3]) * (1.f / DMODEL);
    float inv = rsqrtf(var + 1e-5f);

    float4 gv = *(const float4*)&g[c0];
    float4 bv = *(const float4*)&bb[c0];
    float4 yv;
    yv.x = dx * inv * gv.x + bv.x;
    yv.y = dy * inv * gv.y + bv.y;
    yv.z = dz * inv * gv.z + bv.z;
    yv.w = dw * inv * gv.w + bv.w;
    *(float4*)&y[(size_t)row * DMODEL + c0] = yv;
}

// ---------------------------------------------------------------------------
extern "C" void kernel_launch(void* const* d_in, const int* in_sizes, int n_in,
                              void* d_out, int out_size)
{
    const float* Q    = (const float*)d_in[0];
    const float* K    = (const float*)d_in[1];
    const int*   mask = (const int*)  d_in[2];
    const float* Wq   = (const float*)d_in[3];
    const float* bq   = (const float*)d_in[4];
    const float* Wk   = (const float*)d_in[5];
    const float* bk   = (const float*)d_in[6];
    const float* Wv   = (const float*)d_in[7];
    const float* bv   = (const float*)d_in[8];
    const float* Wo   = (const float*)d_in[9];
    const float* bo   = (const float*)d_in[10];
    const float* g0   = (const float*)d_in[11];
    const float* b0   = (const float*)d_in[12];
    const float* g1   = (const float*)d_in[13];
    const float* b1   = (const float*)d_in[14];

    float *gq, *gk, *gv, *go, *gl, *gt;
    cudaGetSymbolAddress((void**)&gq, g_q);
    cudaGetSymbolAddress((void**)&gk, g_k);
    cudaGetSymbolAddress((void**)&gv, g_v);
    cudaGetSymbolAddress((void**)&go, g_o);
    cudaGetSymbolAddress((void**)&gl, g_ln0);
    cudaGetSymbolAddress((void**)&gt, g_tmp);

    cudaFuncSetAttribute(gemm_mma_kernel, cudaFuncAttributeMaxDynamicSharedMemorySize,
                         GEMM_DSMEM);
    cudaFuncSetAttribute(attn_kernel, cudaFuncAttributeMaxDynamicSharedMemorySize,
                         ATTN_SMEM);

    dim3 ggrid(DMODEL / TCN, NROWS / TCM);   // (8, 64)

    gemm_mma_kernel<<<ggrid, 256, GEMM_DSMEM>>>(Q, Wq, bq, gq, 0);
    gemm_mma_kernel<<<ggrid, 256, GEMM_DSMEM>>>(K, Wk, bk, gk, 0);
    gemm_mma_kernel<<<ggrid, 256, GEMM_DSMEM>>>(K, Wv, bv, gv, 0);

    attn_kernel<<<dim3(NTOK / TQ, NHEAD, BATCH), 256, ATTN_SMEM>>>(gq, gk, gv, mask, go);

    ln_kernel<<<NROWS, 128>>>(go, nullptr, g0, b0, gl);
    gemm_mma_kernel<<<ggrid, 256, GEMM_DSMEM>>>(gl, Wo, bo, gt, 1);
    ln_kernel<<<NROWS, 128>>>(gl, gt, g1, b1, (float*)d_out);
}